// round 2
// baseline (speedup 1.0000x reference)
#include <cuda_runtime.h>
#include <cuda_bf16.h>
#include <cstdint>

#define INPUT_DIM 16384
#define EMB 1024
#define BATCH 4096

// ---------------- device scratch (no allocs allowed) ----------------
__device__ __align__(16) unsigned short g_comb[INPUT_DIM];    // e | (neg<<15) per row j
__device__ __align__(16) unsigned short g_packed[INPUT_DIM];  // bucket-grouped: j | (neg<<15)
__device__ int g_count[EMB];
__device__ int g_start[EMB + 1];
__device__ int g_cursor[EMB];

// ---------------- K0: zero histogram ----------------
__global__ void k_zero() {
    g_count[threadIdx.x] = 0;
}

// ---------------- K1: extract (bucket, sign) per input feature row ----------------
// one warp per row of hashProj [INPUT_DIM, EMB]
__global__ void k_extract(const float* __restrict__ hp) {
    int warp = (blockIdx.x * blockDim.x + threadIdx.x) >> 5;
    int lane = threadIdx.x & 31;
    if (warp >= INPUT_DIM) return;

    const float4* row = reinterpret_cast<const float4*>(hp + (size_t)warp * EMB);
    int   my_e  = 0;
    unsigned my_neg = 0;
    bool  has   = false;
#pragma unroll
    for (int i = 0; i < 8; i++) {
        int idx4 = lane + i * 32;           // float4 index, 256 per row
        float4 v = row[idx4];
        int base = idx4 * 4;
        if (v.x != 0.0f) { my_e = base + 0; my_neg = (v.x < 0.0f); has = true; }
        if (v.y != 0.0f) { my_e = base + 1; my_neg = (v.y < 0.0f); has = true; }
        if (v.z != 0.0f) { my_e = base + 2; my_neg = (v.z < 0.0f); has = true; }
        if (v.w != 0.0f) { my_e = base + 3; my_neg = (v.w < 0.0f); has = true; }
    }
    unsigned mask = __ballot_sync(0xffffffffu, has);
    if (mask == 0) {            // defensive: all-zero row contributes nothing -> bucket 0, sign + (value 0 anyway impossible here)
        if (lane == 0) { g_comb[warp] = 0; atomicAdd(&g_count[0], 1); }
        return;
    }
    int src = __ffs(mask) - 1;
    int e        = __shfl_sync(0xffffffffu, my_e, src);
    unsigned neg = __shfl_sync(0xffffffffu, my_neg, src);
    if (lane == 0) {
        g_comb[warp] = (unsigned short)(e | (neg << 15));
        atomicAdd(&g_count[e], 1);
    }
}

// ---------------- K2: exclusive scan over 1024 buckets (one block) ----------------
__global__ void k_scan() {
    __shared__ int s[EMB];
    int t = threadIdx.x;
    int c = g_count[t];
    s[t] = c;
    __syncthreads();
#pragma unroll
    for (int off = 1; off < EMB; off <<= 1) {
        int a = (t >= off) ? s[t - off] : 0;
        __syncthreads();
        s[t] += a;
        __syncthreads();
    }
    int excl = s[t] - c;
    g_start[t]  = excl;
    g_cursor[t] = excl;
    if (t == EMB - 1) g_start[EMB] = s[t];
}

// ---------------- K3: scatter j's into bucket-grouped packed list ----------------
__global__ void k_scatter() {
    int j = blockIdx.x * blockDim.x + threadIdx.x;
    if (j >= INPUT_DIM) return;
    unsigned c = g_comb[j];
    int e = c & (EMB - 1);
    int pos = atomicAdd(&g_cursor[e], 1);
    g_packed[pos] = (unsigned short)(j | (c & 0x8000u));
}

// ---------------- K4: main gather — one block per batch row ----------------
// smem: x row (64KB f32) + packed list (32KB u16) + starts (4.1KB)
#define GTHREADS 512
__global__ __launch_bounds__(GTHREADS, 2)
void k_gather(const float* __restrict__ x, float* __restrict__ out) {
    extern __shared__ unsigned char smem[];
    float*          xs = reinterpret_cast<float*>(smem);                 // [INPUT_DIM]
    unsigned short* ps = reinterpret_cast<unsigned short*>(xs + INPUT_DIM); // [INPUT_DIM]
    int*            ss = reinterpret_cast<int*>(ps + INPUT_DIM);         // [EMB+1]

    int b = blockIdx.x;
    int t = threadIdx.x;

    // stage bucket starts
    for (int i = t; i < EMB + 1; i += GTHREADS) ss[i] = g_start[i];
    // stage packed index list (32KB) as uint4
    {
        const uint4* gp = reinterpret_cast<const uint4*>(g_packed);
        uint4* sp = reinterpret_cast<uint4*>(ps);
#pragma unroll
        for (int i = t; i < INPUT_DIM * 2 / 16; i += GTHREADS) sp[i] = gp[i];
    }
    // stage x row (64KB) as float4
    {
        const float4* gx = reinterpret_cast<const float4*>(x + (size_t)b * INPUT_DIM);
        float4* sx = reinterpret_cast<float4*>(xs);
#pragma unroll
        for (int i = t; i < INPUT_DIM / 4; i += GTHREADS) sx[i] = gx[i];
    }
    __syncthreads();

    float* o = out + (size_t)b * EMB;
#pragma unroll
    for (int r = 0; r < EMB / GTHREADS; r++) {
        int e = t + r * GTHREADS;
        int k0 = ss[e], k1 = ss[e + 1];
        float acc = 0.0f;
        for (int k = k0; k < k1; k++) {
            unsigned p = ps[k];
            float v = xs[p & 0x3FFFu];
            // flip sign bit if bit15 set: add becomes subtract, branchless
            acc += __uint_as_float(__float_as_uint(v) ^ ((p & 0x8000u) << 16));
        }
        o[e] = acc;
    }
}

extern "C" void kernel_launch(void* const* d_in, const int* in_sizes, int n_in,
                              void* d_out, int out_size) {
    const float* x  = (const float*)d_in[0];   // [BATCH, INPUT_DIM]
    const float* hp = (const float*)d_in[1];   // [INPUT_DIM, EMB]
    float* out = (float*)d_out;                // [BATCH, EMB]

    int smem = INPUT_DIM * 4 + INPUT_DIM * 2 + (EMB + 1) * 4; // 102404 B
    cudaFuncSetAttribute(k_gather, cudaFuncAttributeMaxDynamicSharedMemorySize, smem);

    k_zero<<<1, EMB>>>();
    k_extract<<<(INPUT_DIM * 32) / 256, 256>>>(hp);
    k_scan<<<1, EMB>>>();
    k_scatter<<<INPUT_DIM / 256, 256>>>();
    k_gather<<<BATCH, GTHREADS, smem>>>(x, out);
}

// round 3
// speedup vs baseline: 1.3873x; 1.3873x over previous
#include <cuda_runtime.h>
#include <cuda_bf16.h>
#include <cstdint>

#define INPUT_DIM 16384
#define EMB 1024
#define BATCH 4096
#define XS_MAX (INPUT_DIM + EMB * 3)   // 19456 floats, padded-position upper bound (<32768, fits 15 bits)

// ---------------- device scratch (no allocs allowed) ----------------
__device__ unsigned short g_comb[INPUT_DIM];                 // e | (neg<<15) per feature j
__device__ __align__(16) unsigned short g_pos[INPUT_DIM];    // padded position | (neg<<15), indexed by j
__device__ int g_count[EMB];
__device__ int g_astart[EMB];                                // padded (mult-of-4) bucket start
__device__ int g_len[EMB];                                   // actual bucket length
__device__ int g_cursor[EMB];

// ---------------- K0: zero histogram ----------------
__global__ void k_zero() { g_count[threadIdx.x] = 0; }

// ---------------- K1: extract (bucket, sign) per feature row (one warp / row) ----------------
__global__ void k_extract(const float* __restrict__ hp) {
    int warp = (blockIdx.x * blockDim.x + threadIdx.x) >> 5;
    int lane = threadIdx.x & 31;
    if (warp >= INPUT_DIM) return;

    const float4* row = reinterpret_cast<const float4*>(hp + (size_t)warp * EMB);
    int my_e = 0; unsigned my_neg = 0; bool has = false;
#pragma unroll
    for (int i = 0; i < 8; i++) {
        int idx4 = lane + i * 32;
        float4 v = row[idx4];
        int base = idx4 * 4;
        if (v.x != 0.0f) { my_e = base + 0; my_neg = (v.x < 0.0f); has = true; }
        if (v.y != 0.0f) { my_e = base + 1; my_neg = (v.y < 0.0f); has = true; }
        if (v.z != 0.0f) { my_e = base + 2; my_neg = (v.z < 0.0f); has = true; }
        if (v.w != 0.0f) { my_e = base + 3; my_neg = (v.w < 0.0f); has = true; }
    }
    unsigned mask = __ballot_sync(0xffffffffu, has);
    if (mask == 0) { if (lane == 0) { g_comb[warp] = 0; atomicAdd(&g_count[0], 1); } return; }
    int src = __ffs(mask) - 1;
    int e        = __shfl_sync(0xffffffffu, my_e, src);
    unsigned neg = __shfl_sync(0xffffffffu, my_neg, src);
    if (lane == 0) {
        g_comb[warp] = (unsigned short)(e | (neg << 15));
        atomicAdd(&g_count[e], 1);
    }
}

// ---------------- K2: exclusive scan of 4-padded bucket lengths (one block) ----------------
__global__ void k_scan() {
    __shared__ int s[EMB];
    int t = threadIdx.x;
    int c = g_count[t];
    int pl = (c + 3) & ~3;           // pad to multiple of 4 for float4 reduction
    s[t] = pl;
    __syncthreads();
#pragma unroll
    for (int off = 1; off < EMB; off <<= 1) {
        int a = (t >= off) ? s[t - off] : 0;
        __syncthreads();
        s[t] += a;
        __syncthreads();
    }
    int start = s[t] - pl;
    g_astart[t] = start;
    g_len[t]    = c;
    g_cursor[t] = start;
}

// ---------------- K3: assign each feature j its padded position ----------------
__global__ void k_assign() {
    int j = blockIdx.x * blockDim.x + threadIdx.x;
    if (j >= INPUT_DIM) return;
    unsigned c = g_comb[j];
    int e = c & (EMB - 1);
    int pos = atomicAdd(&g_cursor[e], 1);
    g_pos[j] = (unsigned short)(pos | (c & 0x8000u));
}

// ---------------- K4: main kernel — scatter-on-stage, contiguous f4 reduce ----------------
#define GTHREADS 512
__global__ __launch_bounds__(GTHREADS, 2)
void k_gather(const float* __restrict__ x, float* __restrict__ out) {
    extern __shared__ float xs[];    // [XS_MAX] bucket-sorted, sign-applied copy of row b

    int b = blockIdx.x;
    int t = threadIdx.x;

    // Phase A: zero pad slots (<=3 per bucket) so the f4 reduce can read them.
    for (int e = t; e < EMB; e += GTHREADS) {
        int s0 = __ldg(&g_astart[e]);
        int l  = __ldg(&g_len[e]);
        int pl = (l + 3) & ~3;
        for (int k = s0 + l; k < s0 + pl; k++) xs[k] = 0.0f;
    }

    // Phase B: coalesced load of x row + permuted, sign-applied scatter into smem.
    {
        const float4* gx = reinterpret_cast<const float4*>(x + (size_t)b * INPUT_DIM);
        const uint2*  gp = reinterpret_cast<const uint2*>(g_pos);   // 4 x u16 per load
#pragma unroll
        for (int i = t; i < INPUT_DIM / 4; i += GTHREADS) {
            float4 v = gx[i];
            uint2  p = gp[i];
            unsigned p0 = p.x & 0xFFFFu, p1 = p.x >> 16;
            unsigned p2 = p.y & 0xFFFFu, p3 = p.y >> 16;
            // sign-apply: flip fp32 sign bit if bit15 of pos entry is set
            xs[p0 & 0x7FFFu] = __uint_as_float(__float_as_uint(v.x) ^ ((p0 & 0x8000u) << 16));
            xs[p1 & 0x7FFFu] = __uint_as_float(__float_as_uint(v.y) ^ ((p1 & 0x8000u) << 16));
            xs[p2 & 0x7FFFu] = __uint_as_float(__float_as_uint(v.z) ^ ((p2 & 0x8000u) << 16));
            xs[p3 & 0x7FFFu] = __uint_as_float(__float_as_uint(v.w) ^ ((p3 & 0x8000u) << 16));
        }
    }
    __syncthreads();

    // Phase C: contiguous float4 streaming reduction per bucket (2 buckets/thread).
    float* o = out + (size_t)b * EMB;
#pragma unroll
    for (int r = 0; r < EMB / GTHREADS; r++) {
        int e  = t + r * GTHREADS;
        int s0 = __ldg(&g_astart[e]);
        int pl = (__ldg(&g_len[e]) + 3) & ~3;
        const float4* xs4 = reinterpret_cast<const float4*>(xs) + (s0 >> 2);
        float acc = 0.0f;
        int n4 = pl >> 2;
        for (int i = 0; i < n4; i++) {
            float4 v = xs4[i];
            acc += (v.x + v.y) + (v.z + v.w);
        }
        o[e] = acc;
    }
}

extern "C" void kernel_launch(void* const* d_in, const int* in_sizes, int n_in,
                              void* d_out, int out_size) {
    const float* x  = (const float*)d_in[0];   // [BATCH, INPUT_DIM]
    const float* hp = (const float*)d_in[1];   // [INPUT_DIM, EMB]
    float* out = (float*)d_out;                // [BATCH, EMB]

    int smem = XS_MAX * (int)sizeof(float);    // 77824 B -> 2 blocks/SM
    cudaFuncSetAttribute(k_gather, cudaFuncAttributeMaxDynamicSharedMemorySize, smem);

    k_zero<<<1, EMB>>>();
    k_extract<<<(INPUT_DIM * 32) / 256, 256>>>(hp);
    k_scan<<<1, EMB>>>();
    k_assign<<<INPUT_DIM / 256, 256>>>();
    k_gather<<<BATCH, GTHREADS, smem>>>(x, out);
}